// round 3
// baseline (speedup 1.0000x reference)
#include <cuda_runtime.h>
#include <cuda_bf16.h>
#include <cstdint>

// Problem constants (fixed by the dataset)
#define NN   100000      // nodes
#define EE   1600000     // edges (no self loops)
#define INC  256
#define HID  128
#define OUTC 64

// -------- scratch (static __device__ — allocation is forbidden) --------
static __device__ __align__(256) float d_deg [NN];
static __device__ __align__(256) float d_dinv[NN];
static __device__ __align__(256) float d_Hpre[(size_t)NN * HID];   // x @ W1
static __device__ __align__(256) float d_Hagg[(size_t)NN * HID];   // edge agg of Hpre
static __device__ __align__(256) float d_H1  [(size_t)NN * HID];   // leakyrelu(...)
static __device__ __align__(256) float d_G   [(size_t)NN * HID];   // H1 @ [Wmu|Wlv]
static __device__ __align__(256) float d_Wcat[HID * HID];          // [Wmu|Wlv]

// ---------------- small utility kernels ----------------
__global__ void k_init_deg(int n) {
    int i = blockIdx.x * blockDim.x + threadIdx.x;
    if (i < n) d_deg[i] = 1.0f;                      // self loop
}

__global__ void k_count_deg(const int* __restrict__ dst, int e) {
    int i = blockIdx.x * blockDim.x + threadIdx.x;
    if (i < e) atomicAdd(&d_deg[dst[i]], 1.0f);
}

__global__ void k_dinv(int n) {
    int i = blockIdx.x * blockDim.x + threadIdx.x;
    if (i < n) d_dinv[i] = rsqrtf(d_deg[i]);         // deg >= 1 always
}

__global__ void k_zero4(float* __restrict__ p, int n4) {
    int i = blockIdx.x * blockDim.x + threadIdx.x;
    if (i < n4) ((float4*)p)[i] = make_float4(0.f, 0.f, 0.f, 0.f);
}

__global__ void k_build_wcat(const float* __restrict__ Wmu,
                             const float* __restrict__ Wlv) {
    int i = blockIdx.x * blockDim.x + threadIdx.x;   // i < 128*128
    if (i < HID * HID) {
        int k = i / HID, c = i % HID;
        d_Wcat[i] = (c < OUTC) ? Wmu[k * OUTC + c] : Wlv[k * OUTC + (c - OUTC)];
    }
}

// ---------------- SGEMM: C[M,128] = A[M,K] @ B[K,128] ----------------
// BM=64, BN=128, BK=16, TM=8, TN=4, 256 threads
template <int K>
__global__ void k_sgemm_n128(const float* __restrict__ A,
                             const float* __restrict__ B,
                             float* __restrict__ C, int M) {
    constexpr int BM = 64, BN = 128, BK = 16;
    __shared__ float As[BK][BM + 2];   // padded: conflict-free transposed stores
    __shared__ float Bs[BK][BN];

    const int tid = threadIdx.x;
    const int tn  = tid & 31;          // 0..31  -> cols tn*4 .. tn*4+3
    const int tm  = tid >> 5;          // 0..7   -> rows tm*8 .. tm*8+7
    const int block_row = blockIdx.x * BM;

    const int arow = tid >> 2;         // 0..63
    const int acol = (tid & 3) * 4;    // 0,4,8,12

    float acc[8][4] = {};

    for (int k0 = 0; k0 < K; k0 += BK) {
        // load A tile (64 x 16), transposed into As
        int gr = block_row + arow;
        float4 av = (gr < M) ? *(const float4*)(A + (size_t)gr * K + k0 + acol)
                             : make_float4(0.f, 0.f, 0.f, 0.f);
        As[acol + 0][arow] = av.x;
        As[acol + 1][arow] = av.y;
        As[acol + 2][arow] = av.z;
        As[acol + 3][arow] = av.w;
        // load B tile (16 x 128): 512 float4, 2 per thread
        #pragma unroll
        for (int i = 0; i < 2; i++) {
            int idx  = tid + i * 256;
            int brow = idx >> 5;
            int bcol = (idx & 31) * 4;
            *(float4*)&Bs[brow][bcol] =
                *(const float4*)(B + (size_t)(k0 + brow) * BN + bcol);
        }
        __syncthreads();

        #pragma unroll
        for (int kk = 0; kk < BK; kk++) {
            float a[8];
            #pragma unroll
            for (int j = 0; j < 8; j++) a[j] = As[kk][tm * 8 + j];
            float4 b = *(float4*)&Bs[kk][tn * 4];
            #pragma unroll
            for (int j = 0; j < 8; j++) {
                acc[j][0] += a[j] * b.x;
                acc[j][1] += a[j] * b.y;
                acc[j][2] += a[j] * b.z;
                acc[j][3] += a[j] * b.w;
            }
        }
        __syncthreads();
    }

    #pragma unroll
    for (int j = 0; j < 8; j++) {
        int gr = block_row + tm * 8 + j;
        if (gr < M)
            *(float4*)(C + (size_t)gr * BN + tn * 4) =
                make_float4(acc[j][0], acc[j][1], acc[j][2], acc[j][3]);
    }
}

// vector reduction helper: 16B global atomic add, explicit global space
static __device__ __forceinline__ void red_add_v4(float* p, float a, float b,
                                                  float c, float d) {
    asm volatile("red.global.add.v4.f32 [%0], {%1,%2,%3,%4};" ::
                 "l"(__cvta_generic_to_global(p)),
                 "f"(a), "f"(b), "f"(c), "f"(d) : "memory");
}

// ---------------- edge aggregation (layer 1) ----------------
// one thread per (edge, float4-chunk): 32 chunks cover the 128-wide row
__global__ void k_agg1(const int* __restrict__ src,
                       const int* __restrict__ dst, int e) {
    int t = blockIdx.x * blockDim.x + threadIdx.x;
    int ed = t >> 5;
    if (ed >= e) return;
    int c = t & 31;
    int s = src[ed];
    int d = dst[ed];
    float nrm = d_dinv[s] * d_dinv[d];
    float4 v = *(const float4*)(d_Hpre + (size_t)s * HID + c * 4);
    float* p = d_Hagg + (size_t)d * HID + c * 4;
    red_add_v4(p, v.x * nrm, v.y * nrm, v.z * nrm, v.w * nrm);
}

// epilogue 1: H1 = leaky_relu(Hagg + Hpre*dinv^2 + b1)
__global__ void k_epi1(const float* __restrict__ b1, int n) {
    int t = blockIdx.x * blockDim.x + threadIdx.x;   // n*32 threads
    int i = t >> 5;
    if (i >= n) return;
    int c = t & 31;
    float di = d_dinv[i];
    float d2 = di * di;
    size_t off = (size_t)i * HID + c * 4;
    float4 a  = *(const float4*)(d_Hagg + off);
    float4 h  = *(const float4*)(d_Hpre + off);
    float4 bb = *(const float4*)(b1 + c * 4);
    float4 r;
    r.x = a.x + h.x * d2 + bb.x;
    r.y = a.y + h.y * d2 + bb.y;
    r.z = a.z + h.z * d2 + bb.z;
    r.w = a.w + h.w * d2 + bb.w;
    r.x = r.x >= 0.f ? r.x : 0.01f * r.x;
    r.y = r.y >= 0.f ? r.y : 0.01f * r.y;
    r.z = r.z >= 0.f ? r.z : 0.01f * r.z;
    r.w = r.w >= 0.f ? r.w : 0.01f * r.w;
    *(float4*)(d_H1 + off) = r;
}

// ---------------- edge aggregation (layers 2+3, fused) ----------------
// G cols 0..63 -> mu, cols 64..127 -> logvar (two halves of d_out)
__global__ void k_agg2(const int* __restrict__ src,
                       const int* __restrict__ dst,
                       float* __restrict__ mu, float* __restrict__ lv, int e) {
    int t = blockIdx.x * blockDim.x + threadIdx.x;
    int ed = t >> 5;
    if (ed >= e) return;
    int c = t & 31;
    int s = src[ed];
    int d = dst[ed];
    float nrm = d_dinv[s] * d_dinv[d];
    float4 v = *(const float4*)(d_G + (size_t)s * HID + c * 4);
    float* p = (c < 16) ? (mu + (size_t)d * OUTC + c * 4)
                        : (lv + (size_t)d * OUTC + (c - 16) * 4);
    red_add_v4(p, v.x * nrm, v.y * nrm, v.z * nrm, v.w * nrm);
}

// epilogue 2: out += G*dinv^2 + bias (in place on d_out halves)
__global__ void k_epi2(float* __restrict__ mu, float* __restrict__ lv,
                       const float* __restrict__ bmu,
                       const float* __restrict__ blv, int n) {
    int t = blockIdx.x * blockDim.x + threadIdx.x;   // n*32 threads
    int i = t >> 5;
    if (i >= n) return;
    int c = t & 31;
    float di = d_dinv[i];
    float d2 = di * di;
    float4 g = *(const float4*)(d_G + (size_t)i * HID + c * 4);
    float* p;
    float4 bb;
    if (c < 16) { p = mu + (size_t)i * OUTC + c * 4;        bb = *(const float4*)(bmu + c * 4); }
    else        { p = lv + (size_t)i * OUTC + (c - 16) * 4; bb = *(const float4*)(blv + (c - 16) * 4); }
    float4 o = *(float4*)p;
    o.x += g.x * d2 + bb.x;
    o.y += g.y * d2 + bb.y;
    o.z += g.z * d2 + bb.z;
    o.w += g.w * d2 + bb.w;
    *(float4*)p = o;
}

// ---------------- launch ----------------
extern "C" void kernel_launch(void* const* d_in, const int* in_sizes, int n_in,
                              void* d_out, int out_size) {
    const float* x   = (const float*)d_in[0];
    const int*   ei  = (const int*)d_in[1];     // int32! (JAX x64 disabled)
    const float* W1  = (const float*)d_in[2];
    const float* b1  = (const float*)d_in[3];
    const float* Wmu = (const float*)d_in[4];
    const float* bmu = (const float*)d_in[5];
    const float* Wlv = (const float*)d_in[6];
    const float* blv = (const float*)d_in[7];

    const int e = in_sizes[1] / 2;        // 1,600,000
    const int n = in_sizes[0] / INC;      // 100,000

    const int* src = ei;
    const int* dst = ei + e;

    float* mu = (float*)d_out;
    float* lv = mu + (size_t)n * OUTC;

    // REAL device addresses for the __device__ scratch symbols.
    float *hpre_p, *hagg_p, *h1_p, *g_p, *wcat_p;
    cudaGetSymbolAddress((void**)&hpre_p, d_Hpre);
    cudaGetSymbolAddress((void**)&hagg_p, d_Hagg);
    cudaGetSymbolAddress((void**)&h1_p,   d_H1);
    cudaGetSymbolAddress((void**)&g_p,    d_G);
    cudaGetSymbolAddress((void**)&wcat_p, d_Wcat);

    const int T = 256;

    // degree + norm
    k_init_deg<<<(n + T - 1) / T, T>>>(n);
    k_count_deg<<<(e + T - 1) / T, T>>>(dst, e);
    k_dinv<<<(n + T - 1) / T, T>>>(n);

    // GEMM1: Hpre = x @ W1
    k_sgemm_n128<INC><<<(n + 63) / 64, 256>>>(x, W1, hpre_p, n);

    // zero aggregation buffer, aggregate, epilogue
    {
        int n4 = n * (HID / 4);
        k_zero4<<<(n4 + T - 1) / T, T>>>(hagg_p, n4);
    }
    {
        long long tot = (long long)e * 32;
        k_agg1<<<(unsigned)((tot + T - 1) / T), T>>>(src, dst, e);
    }
    k_epi1<<<(n * 32 + T - 1) / T, T>>>(b1, n);

    // build Wcat and GEMM2: G = H1 @ [Wmu|Wlv]
    k_build_wcat<<<(HID * HID + T - 1) / T, T>>>(Wmu, Wlv);
    k_sgemm_n128<HID><<<(n + 63) / 64, 256>>>(h1_p, wcat_p, g_p, n);

    // zero d_out, aggregate into it, epilogue adds self-loop + bias
    {
        int n4 = out_size / 4;
        k_zero4<<<(n4 + T - 1) / T, T>>>((float*)d_out, n4);
    }
    {
        long long tot = (long long)e * 32;
        k_agg2<<<(unsigned)((tot + T - 1) / T), T>>>(src, dst, mu, lv, e);
    }
    k_epi2<<<(n * 32 + T - 1) / T, T>>>(mu, lv, bmu, blv, n);
}

// round 4
// speedup vs baseline: 1.6273x; 1.6273x over previous
#include <cuda_runtime.h>
#include <cstdint>

#define NN   100000
#define EE   1600000
#define INC  256
#define HID  128
#define OUTC 64
#define SCAN_B 128
#define MAXBLK 1024          // >= ceil(NN/SCAN_B) = 782

// -------- scratch (__device__ globals; allocation is forbidden) --------
static __device__ __align__(256) int   d_degi[NN];
static __device__ __align__(256) int   d_off [NN + 1];
static __device__ __align__(256) int   d_cur [NN];
static __device__ __align__(256) int   d_csr [EE];
static __device__ __align__(256) int   d_bsum [MAXBLK];
static __device__ __align__(256) int   d_bsum2[MAXBLK];
static __device__ __align__(256) float d_dinv[NN];
static __device__ __align__(256) float d_Hs [(size_t)NN * HID];  // (x@W1)*dinv
static __device__ __align__(256) float d_H1 [(size_t)NN * HID];  // leaky(agg1)
static __device__ __align__(256) float d_Gs [(size_t)NN * HID];  // (H1@Wcat)*dinv
static __device__ __align__(256) float d_Wcat[HID * HID];

// ---------------- graph preprocessing ----------------
__global__ void k_zero_deg(int n) {
    int i = blockIdx.x * blockDim.x + threadIdx.x;
    if (i < n) d_degi[i] = 0;
}

__global__ void k_degcnt(const int* __restrict__ dst, int e) {
    int i = blockIdx.x * blockDim.x + threadIdx.x;
    if (i < e) atomicAdd(&d_degi[dst[i]], 1);
}

__global__ void k_dinv(int n) {
    int i = blockIdx.x * blockDim.x + threadIdx.x;
    if (i < n) d_dinv[i] = rsqrtf((float)(d_degi[i] + 1));  // +1 self loop
}

// three-phase exclusive scan of d_degi -> d_off (d_off[0]=0, d_off[n]=E)
__global__ void k_scanA(int n) {
    __shared__ int sm[SCAN_B];
    int b = blockIdx.x, t = threadIdx.x, gi = b * SCAN_B + t;
    int v = (gi < n) ? d_degi[gi] : 0;
    sm[t] = v; __syncthreads();
    #pragma unroll
    for (int s = 1; s < SCAN_B; s <<= 1) {
        int u = (t >= s) ? sm[t - s] : 0;
        __syncthreads(); sm[t] += u; __syncthreads();
    }
    if (gi < n) d_off[gi + 1] = sm[t];     // local inclusive, fixed in scanC
    if (t == SCAN_B - 1) d_bsum[b] = sm[t];
}

__global__ void k_scanB(int nblk) {
    __shared__ int sm[MAXBLK];
    int t = threadIdx.x;
    int v = (t < nblk) ? d_bsum[t] : 0;
    sm[t] = v; __syncthreads();
    #pragma unroll
    for (int s = 1; s < MAXBLK; s <<= 1) {
        int u = (t >= s) ? sm[t - s] : 0;
        __syncthreads(); sm[t] += u; __syncthreads();
    }
    if (t < nblk) d_bsum2[t] = sm[t] - v;  // exclusive block offsets
    if (t == 0) d_off[0] = 0;
}

__global__ void k_scanC(int n) {
    int b = blockIdx.x, t = threadIdx.x, gi = b * SCAN_B + t;
    if (gi < n) {
        int o = d_off[gi + 1] + d_bsum2[b];
        d_off[gi + 1] = o;
        d_cur[gi] = o - d_degi[gi];        // = exclusive offset (CSR cursor)
    }
}

__global__ void k_scatter(const int* __restrict__ src,
                          const int* __restrict__ dst, int e) {
    int i = blockIdx.x * blockDim.x + threadIdx.x;
    if (i < e) {
        int d = dst[i];
        int pos = atomicAdd(&d_cur[d], 1);
        d_csr[pos] = src[i];
    }
}

__global__ void k_build_wcat(const float* __restrict__ Wmu,
                             const float* __restrict__ Wlv) {
    int i = blockIdx.x * blockDim.x + threadIdx.x;
    if (i < HID * HID) {
        int k = i / HID, c = i % HID;
        d_Wcat[i] = (c < OUTC) ? Wmu[k * OUTC + c] : Wlv[k * OUTC + (c - OUTC)];
    }
}

// -------- SGEMM: C[M,128] = (A[M,K] @ B[K,128]) * dinv[row] --------
// BM=128, BN=128, BK=16, 256 threads, 8x8 per thread
template <int K>
__global__ void __launch_bounds__(256)
k_gemm_scaled(const float* __restrict__ A, const float* __restrict__ B,
              float* __restrict__ C, const float* __restrict__ dinv, int M) {
    constexpr int BM = 128, BN = 128, BK = 16;
    __shared__ float As[BK][BM + 2];
    __shared__ float Bs[BK][BN];

    const int tid = threadIdx.x;
    const int tx  = tid & 15;           // col group: cols tx*8 .. tx*8+7
    const int ty  = tid >> 4;           // row group: rows ty*8 .. ty*8+7
    const int row0 = blockIdx.x * BM;
    const int arow = tid >> 2;          // 0..63
    const int acol = (tid & 3) * 4;

    float acc[8][8] = {};

    for (int k0 = 0; k0 < K; k0 += BK) {
        #pragma unroll
        for (int i = 0; i < 2; i++) {
            int r  = arow + i * 64;
            int gr = row0 + r;
            float4 av = (gr < M)
                ? *(const float4*)(A + (size_t)gr * K + k0 + acol)
                : make_float4(0.f, 0.f, 0.f, 0.f);
            As[acol + 0][r] = av.x;
            As[acol + 1][r] = av.y;
            As[acol + 2][r] = av.z;
            As[acol + 3][r] = av.w;
        }
        #pragma unroll
        for (int i = 0; i < 2; i++) {
            int idx  = tid + i * 256;
            int brow = idx >> 5;
            int bcol = (idx & 31) * 4;
            *(float4*)&Bs[brow][bcol] =
                *(const float4*)(B + (size_t)(k0 + brow) * BN + bcol);
        }
        __syncthreads();

        #pragma unroll
        for (int kk = 0; kk < BK; kk++) {
            float a[8], bb[8];
            #pragma unroll
            for (int j = 0; j < 8; j++) a[j] = As[kk][ty * 8 + j];
            *(float4*)&bb[0] = *(float4*)&Bs[kk][tx * 8];
            *(float4*)&bb[4] = *(float4*)&Bs[kk][tx * 8 + 4];
            #pragma unroll
            for (int j = 0; j < 8; j++)
                #pragma unroll
                for (int i = 0; i < 8; i++)
                    acc[j][i] += a[j] * bb[i];
        }
        __syncthreads();
    }

    #pragma unroll
    for (int j = 0; j < 8; j++) {
        int gr = row0 + ty * 8 + j;
        if (gr < M) {
            float s = dinv[gr];
            float4 v0 = make_float4(acc[j][0] * s, acc[j][1] * s,
                                    acc[j][2] * s, acc[j][3] * s);
            float4 v1 = make_float4(acc[j][4] * s, acc[j][5] * s,
                                    acc[j][6] * s, acc[j][7] * s);
            *(float4*)(C + (size_t)gr * BN + tx * 8)     = v0;
            *(float4*)(C + (size_t)gr * BN + tx * 8 + 4) = v1;
        }
    }
}

// -------- CSR aggregation, warp per node, fused epilogues --------
// layer 1: H1[d] = leaky( dinv[d] * (sum_{e} Hs[src] + Hs[d]) + b1 )
__global__ void k_agg1(const float* __restrict__ b1, int n) {
    int d = (blockIdx.x * blockDim.x + threadIdx.x) >> 5;
    int lane = threadIdx.x & 31;
    if (d >= n) return;

    const float4* base = (const float4*)d_Hs;
    float4 acc = base[(size_t)d * 32 + lane];           // self loop
    int beg = d_off[d], end = d_off[d + 1];
    for (int k = beg; k < end; k += 32) {
        int rem = end - k;
        int s = (lane < rem) ? d_csr[k + lane] : 0;
        int cnt = rem < 32 ? rem : 32;
        for (int j = 0; j < cnt; j++) {
            int sj = __shfl_sync(0xffffffffu, s, j);
            float4 v = base[(size_t)sj * 32 + lane];
            acc.x += v.x; acc.y += v.y; acc.z += v.z; acc.w += v.w;
        }
    }
    float sc = d_dinv[d];
    float4 bb = *(const float4*)(b1 + lane * 4);
    float4 r;
    r.x = acc.x * sc + bb.x;
    r.y = acc.y * sc + bb.y;
    r.z = acc.z * sc + bb.z;
    r.w = acc.w * sc + bb.w;
    r.x = r.x >= 0.f ? r.x : 0.01f * r.x;
    r.y = r.y >= 0.f ? r.y : 0.01f * r.y;
    r.z = r.z >= 0.f ? r.z : 0.01f * r.z;
    r.w = r.w >= 0.f ? r.w : 0.01f * r.w;
    *(float4*)(d_H1 + (size_t)d * HID + lane * 4) = r;
}

// layers 2+3: out = dinv[d]*(sum Gs[src] + Gs[d]) + bias, split mu|lv
__global__ void k_agg2(const float* __restrict__ bmu,
                       const float* __restrict__ blv,
                       float* __restrict__ mu, float* __restrict__ lv, int n) {
    int d = (blockIdx.x * blockDim.x + threadIdx.x) >> 5;
    int lane = threadIdx.x & 31;
    if (d >= n) return;

    const float4* base = (const float4*)d_Gs;
    float4 acc = base[(size_t)d * 32 + lane];           // self loop
    int beg = d_off[d], end = d_off[d + 1];
    for (int k = beg; k < end; k += 32) {
        int rem = end - k;
        int s = (lane < rem) ? d_csr[k + lane] : 0;
        int cnt = rem < 32 ? rem : 32;
        for (int j = 0; j < cnt; j++) {
            int sj = __shfl_sync(0xffffffffu, s, j);
            float4 v = base[(size_t)sj * 32 + lane];
            acc.x += v.x; acc.y += v.y; acc.z += v.z; acc.w += v.w;
        }
    }
    float sc = d_dinv[d];
    float4 bb = (lane < 16) ? *(const float4*)(bmu + lane * 4)
                            : *(const float4*)(blv + (lane - 16) * 4);
    float4 r;
    r.x = acc.x * sc + bb.x;
    r.y = acc.y * sc + bb.y;
    r.z = acc.z * sc + bb.z;
    r.w = acc.w * sc + bb.w;
    float* p = (lane < 16) ? (mu + (size_t)d * OUTC + lane * 4)
                           : (lv + (size_t)d * OUTC + (lane - 16) * 4);
    *(float4*)p = r;
}

// ---------------- launch ----------------
extern "C" void kernel_launch(void* const* d_in, const int* in_sizes, int n_in,
                              void* d_out, int out_size) {
    const float* x   = (const float*)d_in[0];
    const int*   ei  = (const int*)d_in[1];     // int32 (JAX x64 disabled)
    const float* W1  = (const float*)d_in[2];
    const float* b1  = (const float*)d_in[3];
    const float* Wmu = (const float*)d_in[4];
    const float* bmu = (const float*)d_in[5];
    const float* Wlv = (const float*)d_in[6];
    const float* blv = (const float*)d_in[7];

    const int e = in_sizes[1] / 2;        // 1,600,000
    const int n = in_sizes[0] / INC;      // 100,000
    const int* src = ei;
    const int* dst = ei + e;

    float* mu = (float*)d_out;
    float* lv = mu + (size_t)n * OUTC;

    float *hs_p, *h1_p, *gs_p, *wcat_p, *dinv_p;
    cudaGetSymbolAddress((void**)&hs_p,   d_Hs);
    cudaGetSymbolAddress((void**)&h1_p,   d_H1);
    cudaGetSymbolAddress((void**)&gs_p,   d_Gs);
    cudaGetSymbolAddress((void**)&wcat_p, d_Wcat);
    cudaGetSymbolAddress((void**)&dinv_p, d_dinv);

    const int T = 256;
    const int nblk = (n + SCAN_B - 1) / SCAN_B;   // 782

    // ---- graph prep: degrees, dinv, CSR ----
    k_zero_deg<<<(n + T - 1) / T, T>>>(n);
    k_degcnt<<<(e + T - 1) / T, T>>>(dst, e);
    k_dinv<<<(n + T - 1) / T, T>>>(n);
    k_scanA<<<nblk, SCAN_B>>>(n);
    k_scanB<<<1, MAXBLK>>>(nblk);
    k_scanC<<<nblk, SCAN_B>>>(n);
    k_scatter<<<(e + T - 1) / T, T>>>(src, dst, e);
    k_build_wcat<<<(HID * HID + T - 1) / T, T>>>(Wmu, Wlv);

    // ---- layer 1 ----
    k_gemm_scaled<INC><<<(n + 127) / 128, 256>>>(x, W1, hs_p, dinv_p, n);
    k_agg1<<<(n * 32 + T - 1) / T, T>>>(b1, n);

    // ---- layers 2+3 (fused) ----
    k_gemm_scaled<HID><<<(n + 127) / 128, 256>>>(h1_p, wcat_p, gs_p, dinv_p, n);
    k_agg2<<<(n * 32 + T - 1) / T, T>>>(bmu, blv, mu, lv, n);
}

// round 6
// speedup vs baseline: 1.7219x; 1.0581x over previous
#include <cuda_runtime.h>
#include <cstdint>

#define NN   100000
#define EE   1600000
#define INC  256
#define HID  128
#define OUTC 64
#define SCAN_B 128
#define MAXBLK 1024

// -------- scratch (__device__ globals; allocation is forbidden) --------
static __device__ __align__(256) int   d_degi[NN];
static __device__ __align__(256) int   d_off [NN + 1];
static __device__ __align__(256) int   d_cur [NN];
static __device__ __align__(256) int   d_csr [EE];
static __device__ __align__(256) int   d_bsum [MAXBLK];
static __device__ __align__(256) int   d_bsum2[MAXBLK];
static __device__ __align__(256) float d_dinv[NN];
static __device__ __align__(256) float d_Hs [(size_t)NN * HID];
static __device__ __align__(256) float d_H1 [(size_t)NN * HID];
static __device__ __align__(256) float d_Gs [(size_t)NN * HID];
static __device__ __align__(256) float d_Wcat[HID * HID];

// ---------------- packed f32x2 helpers ----------------
static __device__ __forceinline__ void ffma2(unsigned long long& d,
                                             unsigned long long a,
                                             unsigned long long b) {
    asm("fma.rn.f32x2 %0, %1, %2, %0;" : "+l"(d) : "l"(a), "l"(b));
}
static __device__ __forceinline__ unsigned long long bcast2(float f) {
    unsigned long long r;
    asm("mov.b64 %0, {%1, %1};" : "=l"(r) : "f"(f));
    return r;
}

// ---------------- graph preprocessing ----------------
__global__ void k_zero_deg(int n) {
    int i = blockIdx.x * blockDim.x + threadIdx.x;
    if (i < n) d_degi[i] = 0;
}
__global__ void k_degcnt(const int* __restrict__ dst, int e) {
    int i = blockIdx.x * blockDim.x + threadIdx.x;
    if (i < e) atomicAdd(&d_degi[dst[i]], 1);
}
__global__ void k_dinv(int n) {
    int i = blockIdx.x * blockDim.x + threadIdx.x;
    if (i < n) d_dinv[i] = rsqrtf((float)(d_degi[i] + 1));  // +1 self loop
}
__global__ void k_scanA(int n) {
    __shared__ int sm[SCAN_B];
    int b = blockIdx.x, t = threadIdx.x, gi = b * SCAN_B + t;
    int v = (gi < n) ? d_degi[gi] : 0;
    sm[t] = v; __syncthreads();
    #pragma unroll
    for (int s = 1; s < SCAN_B; s <<= 1) {
        int u = (t >= s) ? sm[t - s] : 0;
        __syncthreads(); sm[t] += u; __syncthreads();
    }
    if (gi < n) d_off[gi + 1] = sm[t];
    if (t == SCAN_B - 1) d_bsum[b] = sm[t];
}
__global__ void k_scanB(int nblk) {
    __shared__ int sm[MAXBLK];
    int t = threadIdx.x;
    int v = (t < nblk) ? d_bsum[t] : 0;
    sm[t] = v; __syncthreads();
    #pragma unroll
    for (int s = 1; s < MAXBLK; s <<= 1) {
        int u = (t >= s) ? sm[t - s] : 0;
        __syncthreads(); sm[t] += u; __syncthreads();
    }
    if (t < nblk) d_bsum2[t] = sm[t] - v;
    if (t == 0) d_off[0] = 0;
}
__global__ void k_scanC(int n) {
    int b = blockIdx.x, t = threadIdx.x, gi = b * SCAN_B + t;
    if (gi < n) {
        int o = d_off[gi + 1] + d_bsum2[b];
        d_off[gi + 1] = o;
        d_cur[gi] = o - d_degi[gi];
    }
}
__global__ void k_scatter(const int* __restrict__ src,
                          const int* __restrict__ dst, int e) {
    int i = blockIdx.x * blockDim.x + threadIdx.x;
    if (i < e) {
        int d = dst[i];
        int pos = atomicAdd(&d_cur[d], 1);
        d_csr[pos] = src[i];
    }
}
__global__ void k_build_wcat(const float* __restrict__ Wmu,
                             const float* __restrict__ Wlv) {
    int i = blockIdx.x * blockDim.x + threadIdx.x;
    if (i < HID * HID) {
        int k = i / HID, c = i % HID;
        d_Wcat[i] = (c < OUTC) ? Wmu[k * OUTC + c] : Wlv[k * OUTC + (c - OUTC)];
    }
}

// -------- SGEMM (FFMA2): C[M,128] = (A[M,K] @ B[K,128]) [* dinv[row]] --------
// BM=128, BN=128, BK=16, 256 threads; 8 rows x 8 cols per thread, rows packed
// in f32x2 pairs. dinv==nullptr -> no scaling (used when dinv not yet ready).
template <int K>
__global__ void __launch_bounds__(256)
k_gemm_scaled(const float* __restrict__ A, const float* __restrict__ B,
              float* __restrict__ C, const float* __restrict__ dinv, int M) {
    constexpr int BM = 128, BN = 128, BK = 16;
    __shared__ float As[BK][BM + 2];
    __shared__ float Bs[BK][BN];

    const int tid = threadIdx.x;
    const int tx  = tid & 15;
    const int ty  = tid >> 4;
    const int row0 = blockIdx.x * BM;
    const int arow = tid >> 2;
    const int acol = (tid & 3) * 4;

    unsigned long long acc2[4][8] = {};

    for (int k0 = 0; k0 < K; k0 += BK) {
        #pragma unroll
        for (int i = 0; i < 2; i++) {
            int r  = arow + i * 64;
            int gr = row0 + r;
            float4 av = (gr < M)
                ? *(const float4*)(A + (size_t)gr * K + k0 + acol)
                : make_float4(0.f, 0.f, 0.f, 0.f);
            As[acol + 0][r] = av.x;
            As[acol + 1][r] = av.y;
            As[acol + 2][r] = av.z;
            As[acol + 3][r] = av.w;
        }
        #pragma unroll
        for (int i = 0; i < 2; i++) {
            int idx  = tid + i * 256;
            int brow = idx >> 5;
            int bcol = (idx & 31) * 4;
            *(float4*)&Bs[brow][bcol] =
                *(const float4*)(B + (size_t)(k0 + brow) * BN + bcol);
        }
        __syncthreads();

        #pragma unroll
        for (int kk = 0; kk < BK; kk++) {
            unsigned long long a2[4];
            const unsigned long long* ap =
                (const unsigned long long*)&As[kk][ty * 8];
            #pragma unroll
            for (int j = 0; j < 4; j++) a2[j] = ap[j];
            float bv[8];
            *(float4*)&bv[0] = *(float4*)&Bs[kk][tx * 8];
            *(float4*)&bv[4] = *(float4*)&Bs[kk][tx * 8 + 4];
            unsigned long long b2[8];
            #pragma unroll
            for (int i = 0; i < 8; i++) b2[i] = bcast2(bv[i]);
            #pragma unroll
            for (int j = 0; j < 4; j++)
                #pragma unroll
                for (int i = 0; i < 8; i++)
                    ffma2(acc2[j][i], a2[j], b2[i]);
        }
        __syncthreads();
    }

    #pragma unroll
    for (int j = 0; j < 4; j++) {
        int r0 = row0 + ty * 8 + 2 * j;
        float lo[8], hi[8];
        #pragma unroll
        for (int i = 0; i < 8; i++) {
            lo[i] = __uint_as_float((uint32_t)(acc2[j][i] & 0xffffffffull));
            hi[i] = __uint_as_float((uint32_t)(acc2[j][i] >> 32));
        }
        if (r0 < M) {
            float s = dinv ? dinv[r0] : 1.0f;
            float* cp = C + (size_t)r0 * BN + tx * 8;
            *(float4*)cp       = make_float4(lo[0]*s, lo[1]*s, lo[2]*s, lo[3]*s);
            *(float4*)(cp + 4) = make_float4(lo[4]*s, lo[5]*s, lo[6]*s, lo[7]*s);
        }
        if (r0 + 1 < M) {
            float s = dinv ? dinv[r0 + 1] : 1.0f;
            float* cp = C + (size_t)(r0 + 1) * BN + tx * 8;
            *(float4*)cp       = make_float4(hi[0]*s, hi[1]*s, hi[2]*s, hi[3]*s);
            *(float4*)(cp + 4) = make_float4(hi[4]*s, hi[5]*s, hi[6]*s, hi[7]*s);
        }
    }
}

// scale Hs rows by dinv (runs after the prep/GEMM1 join)
__global__ void k_scaleHs(int n) {
    int t = blockIdx.x * blockDim.x + threadIdx.x;
    int i = t >> 5;
    if (i >= n) return;
    int c = t & 31;
    float s = d_dinv[i];
    float4* p = (float4*)(d_Hs + (size_t)i * HID + c * 4);
    float4 v = *p;
    v.x *= s; v.y *= s; v.z *= s; v.w *= s;
    *p = v;
}

// -------- CSR aggregation, warp per node, fused epilogues --------
__global__ void k_agg1(const float* __restrict__ b1, int n) {
    int d = (blockIdx.x * blockDim.x + threadIdx.x) >> 5;
    int lane = threadIdx.x & 31;
    if (d >= n) return;
    const float4* base = (const float4*)d_Hs;
    float4 acc = base[(size_t)d * 32 + lane];
    int beg = d_off[d], end = d_off[d + 1];
    for (int k = beg; k < end; k += 32) {
        int rem = end - k;
        int s = (lane < rem) ? d_csr[k + lane] : 0;
        int cnt = rem < 32 ? rem : 32;
        for (int j = 0; j < cnt; j++) {
            int sj = __shfl_sync(0xffffffffu, s, j);
            float4 v = base[(size_t)sj * 32 + lane];
            acc.x += v.x; acc.y += v.y; acc.z += v.z; acc.w += v.w;
        }
    }
    float sc = d_dinv[d];
    float4 bb = *(const float4*)(b1 + lane * 4);
    float4 r;
    r.x = acc.x * sc + bb.x; r.y = acc.y * sc + bb.y;
    r.z = acc.z * sc + bb.z; r.w = acc.w * sc + bb.w;
    r.x = r.x >= 0.f ? r.x : 0.01f * r.x;
    r.y = r.y >= 0.f ? r.y : 0.01f * r.y;
    r.z = r.z >= 0.f ? r.z : 0.01f * r.z;
    r.w = r.w >= 0.f ? r.w : 0.01f * r.w;
    *(float4*)(d_H1 + (size_t)d * HID + lane * 4) = r;
}

__global__ void k_agg2(const float* __restrict__ bmu,
                       const float* __restrict__ blv,
                       float* __restrict__ mu, float* __restrict__ lv, int n) {
    int d = (blockIdx.x * blockDim.x + threadIdx.x) >> 5;
    int lane = threadIdx.x & 31;
    if (d >= n) return;
    const float4* base = (const float4*)d_Gs;
    float4 acc = base[(size_t)d * 32 + lane];
    int beg = d_off[d], end = d_off[d + 1];
    for (int k = beg; k < end; k += 32) {
        int rem = end - k;
        int s = (lane < rem) ? d_csr[k + lane] : 0;
        int cnt = rem < 32 ? rem : 32;
        for (int j = 0; j < cnt; j++) {
            int sj = __shfl_sync(0xffffffffu, s, j);
            float4 v = base[(size_t)sj * 32 + lane];
            acc.x += v.x; acc.y += v.y; acc.z += v.z; acc.w += v.w;
        }
    }
    float sc = d_dinv[d];
    float4 bb = (lane < 16) ? *(const float4*)(bmu + lane * 4)
                            : *(const float4*)(blv + (lane - 16) * 4);
    float4 r;
    r.x = acc.x * sc + bb.x; r.y = acc.y * sc + bb.y;
    r.z = acc.z * sc + bb.z; r.w = acc.w * sc + bb.w;
    float* p = (lane < 16) ? (mu + (size_t)d * OUTC + lane * 4)
                           : (lv + (size_t)d * OUTC + (lane - 16) * 4);
    *(float4*)p = r;
}

// ---------------- launch ----------------
extern "C" void kernel_launch(void* const* d_in, const int* in_sizes, int n_in,
                              void* d_out, int out_size) {
    const float* x   = (const float*)d_in[0];
    const int*   ei  = (const int*)d_in[1];     // int32 (JAX x64 disabled)
    const float* W1  = (const float*)d_in[2];
    const float* b1  = (const float*)d_in[3];
    const float* Wmu = (const float*)d_in[4];
    const float* bmu = (const float*)d_in[5];
    const float* Wlv = (const float*)d_in[6];
    const float* blv = (const float*)d_in[7];

    const int e = in_sizes[1] / 2;
    const int n = in_sizes[0] / INC;
    const int* src = ei;
    const int* dst = ei + e;

    float* mu = (float*)d_out;
    float* lv = mu + (size_t)n * OUTC;

    float *hs_p, *h1_p, *gs_p, *wcat_p, *dinv_p;
    cudaGetSymbolAddress((void**)&hs_p,   d_Hs);
    cudaGetSymbolAddress((void**)&h1_p,   d_H1);
    cudaGetSymbolAddress((void**)&gs_p,   d_Gs);
    cudaGetSymbolAddress((void**)&wcat_p, d_Wcat);
    cudaGetSymbolAddress((void**)&dinv_p, d_dinv);

    static cudaStream_t s1 = nullptr;
    static cudaEvent_t  evFork = nullptr, evJoin = nullptr;
    if (!s1) {
        cudaStreamCreateWithFlags(&s1, cudaStreamNonBlocking);
        cudaEventCreateWithFlags(&evFork, cudaEventDisableTiming);
        cudaEventCreateWithFlags(&evJoin, cudaEventDisableTiming);
    }

    const int T = 256;
    const int nblk = (n + SCAN_B - 1) / SCAN_B;
    const int gblk = (n + 127) / 128;

    // fork: graph prep on s1 concurrent with GEMM1 on main stream
    cudaEventRecord(evFork, 0);
    cudaStreamWaitEvent(s1, evFork, 0);

    k_zero_deg<<<(n + T - 1) / T, T, 0, s1>>>(n);
    k_degcnt<<<(e + T - 1) / T, T, 0, s1>>>(dst, e);
    k_dinv<<<(n + T - 1) / T, T, 0, s1>>>(n);
    k_scanA<<<nblk, SCAN_B, 0, s1>>>(n);
    k_scanB<<<1, MAXBLK, 0, s1>>>(nblk);
    k_scanC<<<nblk, SCAN_B, 0, s1>>>(n);
    k_scatter<<<(e + T - 1) / T, T, 0, s1>>>(src, dst, e);
    k_build_wcat<<<(HID * HID + T - 1) / T, T, 0, s1>>>(Wmu, Wlv);

    // GEMM1 (unscaled; dinv not ready yet on this branch)
    k_gemm_scaled<INC><<<gblk, 256>>>(x, W1, hs_p, nullptr, n);

    // join, then apply dinv scaling to Hs
    cudaEventRecord(evJoin, s1);
    cudaStreamWaitEvent(0, evJoin, 0);
    k_scaleHs<<<(n * 32 + T - 1) / T, T>>>(n);

    k_agg1<<<(n * 32 + T - 1) / T, T>>>(b1, n);
    k_gemm_scaled<HID><<<gblk, 256>>>(h1_p, wcat_p, gs_p, dinv_p, n);
    k_agg2<<<(n * 32 + T - 1) / T, T>>>(bmu, blv, mu, lv, n);
}